// round 1
// baseline (speedup 1.0000x reference)
#include <cuda_runtime.h>

// WindowAttention fused kernel (Swin-style), fp32 SIMT baseline.
// One CTA per window (4096 CTAs, 256 threads).
//
// Shapes: x[4096,49,192], mask[64,49,49], qkv_w[576,192], qkv_b[576],
//         proj_w[192,192], proj_b[192], bias_table[169,6], rel_index[49,49] i32
// out[4096,49,192] fp32.

namespace {
constexpr int NT   = 49;    // tokens per window
constexpr int C    = 192;   // channels
constexpr int H    = 6;     // heads
constexpr int THREADS = 256;

// smem layout in floats
constexpr int SX_OFF = 0;                 // x / attn-out reuse: [49][192] = 9408
constexpr int SQ_OFF = 9408;              // q: [6][49][32]  = 9408 (scaled)
constexpr int SK_OFF = 18816;             // k: [6][49][36]  = 10584 (padded rows)
constexpr int SV_OFF = 29400;             // v: [6][49][32]  = 9408
constexpr int SA_OFF = 38808;             // attn [6][49][49] = 14406 ; overlaid w-tile [64][196]=12544
constexpr int SM_OFF = 53214;             // mask [49*49] = 2401
constexpr int SMEM_FLOATS = 55615;        // 222,460 bytes
constexpr float QSCALE = 0.17677669529663687f;  // 1/sqrt(32)
}

__global__ __launch_bounds__(THREADS, 1)
void win_attn_kernel(const float* __restrict__ x,
                     const float* __restrict__ mask,
                     const float* __restrict__ qkv_w,
                     const float* __restrict__ qkv_b,
                     const float* __restrict__ proj_w,
                     const float* __restrict__ proj_b,
                     const float* __restrict__ bias_table,
                     const int*   __restrict__ rel_index,
                     float* __restrict__ out)
{
    extern __shared__ float smem[];
    float* sx    = smem + SX_OFF;
    float* sq    = smem + SQ_OFF;
    float* sk    = smem + SK_OFF;
    float* sv    = smem + SV_OFF;
    float* sa    = smem + SA_OFF;
    float* smask = smem + SM_OFF;

    float4* sx4 = reinterpret_cast<float4*>(sx);
    float4* sq4 = reinterpret_cast<float4*>(sq);
    float4* sk4 = reinterpret_cast<float4*>(sk);
    float4* sv4 = reinterpret_cast<float4*>(sv);
    float4* sw4 = reinterpret_cast<float4*>(sa);   // weight-tile overlay, rows of 49 float4 (196 f)

    const int b   = blockIdx.x;
    const int w   = b & 63;              // window index within image (NW=64)
    const int tid = threadIdx.x;

    // ---------------- Phase 0: load x and mask ----------------
    {
        const float4* xin = reinterpret_cast<const float4*>(x + (size_t)b * (NT * C));
        for (int t = tid; t < NT * C / 4; t += THREADS) sx4[t] = __ldg(xin + t);
        const float* mrow = mask + (size_t)w * (NT * NT);
        for (int t = tid; t < NT * NT; t += THREADS) smask[t] = __ldg(mrow + t);
    }

    // ---------------- Phase 1: QKV GEMM (x[49,192] @ qkv_w^T[192,576]) ----------------
    const int rloc = tid & 63;          // output row within tile
    const int nset = tid >> 6;          // which group of 13 tokens

    for (int rt = 0; rt < 9; ++rt) {    // 9 tiles of 64 rows -> 576
        __syncthreads();                // previous tile's sw reads done / sx ready
        {
            const float4* wsrc = reinterpret_cast<const float4*>(qkv_w + rt * 64 * C);
            for (int t = tid; t < 64 * 48; t += THREADS) {
                int rr = t / 48, c4 = t - rr * 48;
                sw4[rr * 49 + c4] = __ldg(wsrc + t);
            }
        }
        __syncthreads();

        const int r = rt * 64 + rloc;   // global qkv row, 0..575
        float acc[13];
        #pragma unroll
        for (int k = 0; k < 13; ++k) acc[k] = 0.f;

        #pragma unroll 4
        for (int c4 = 0; c4 < 48; ++c4) {
            const float4 wv = sw4[rloc * 49 + c4];
            #pragma unroll
            for (int k = 0; k < 13; ++k) {
                int n = nset * 13 + k; if (n > 48) n = 48;   // clamp (dup read, write guarded)
                const float4 xv = sx4[n * 48 + c4];
                acc[k] += wv.x * xv.x + wv.y * xv.y + wv.z * xv.z + wv.w * xv.w;
            }
        }

        const float bb = __ldg(qkv_b + r);
        const int s  = r / 192;         // 0=q 1=k 2=v
        const int hh = (r >> 5) % 6;    // head
        const int d  = r & 31;          // dim within head
        #pragma unroll
        for (int k = 0; k < 13; ++k) {
            const int n = nset * 13 + k;
            if (n < NT) {
                const float val = acc[k] + bb;
                if (s == 0)      sq[(hh * 49 + n) * 32 + d] = val * QSCALE;
                else if (s == 1) sk[(hh * 49 + n) * 36 + d] = val;
                else             sv[(hh * 49 + n) * 32 + d] = val;
            }
        }
    }
    __syncthreads();

    // ---------------- Phase 2: attention logits + bias + mask ----------------
    for (int idx = tid; idx < H * NT * NT; idx += THREADS) {
        const int h   = idx / (NT * NT);
        const int rem = idx - h * (NT * NT);
        const int i   = rem / NT;
        // j = rem - i*NT (implicit via pointers)
        const int j   = rem - i * NT;
        const float4* qp = sq4 + (h * 49 + i) * 8;
        const float4* kp = sk4 + (h * 49 + j) * 9;
        float s = 0.f;
        #pragma unroll
        for (int d4 = 0; d4 < 8; ++d4) {
            const float4 a = qp[d4];
            const float4 kk = kp[d4];
            s += a.x * kk.x + a.y * kk.y + a.z * kk.z + a.w * kk.w;
        }
        const int ri = __ldg(rel_index + rem);
        s += __ldg(bias_table + ri * H + h);
        s += smask[rem];
        sa[idx] = s;
    }
    __syncthreads();

    // ---------------- Phase 3: softmax over j (294 rows of 49) ----------------
    for (int row = tid; row < H * NT; row += THREADS) {
        float* p = sa + row * NT;
        float m = -1e30f;
        #pragma unroll 7
        for (int j = 0; j < NT; ++j) m = fmaxf(m, p[j]);
        float sum = 0.f;
        #pragma unroll 7
        for (int j = 0; j < NT; ++j) { const float e = __expf(p[j] - m); p[j] = e; sum += e; }
        const float inv = __frcp_rn(sum);
        #pragma unroll 7
        for (int j = 0; j < NT; ++j) p[j] *= inv;
    }
    __syncthreads();

    // ---------------- Phase 4: attn @ V -> so[49][192] (reuses sx) ----------------
    float4* so4 = sx4;
    for (int idx = tid; idx < NT * 48; idx += THREADS) {
        const int i  = idx / 48;
        const int c4 = idx - i * 48;
        const int h  = c4 >> 3;
        const int d4 = c4 & 7;
        const float*  ap = sa + (h * 49 + i) * 49;
        const float4* vp = sv4 + (h * 49) * 8 + d4;
        float4 acc = make_float4(0.f, 0.f, 0.f, 0.f);
        #pragma unroll 7
        for (int j = 0; j < NT; ++j) {
            const float a = ap[j];
            const float4 v = vp[j * 8];
            acc.x += a * v.x; acc.y += a * v.y; acc.z += a * v.z; acc.w += a * v.w;
        }
        so4[idx] = acc;
    }
    __syncthreads();

    // ---------------- Phase 5: proj GEMM (so[49,192] @ proj_w^T[192,192]) -> gmem ----------------
    float* yout = out + (size_t)b * (NT * C);
    for (int ct = 0; ct < 3; ++ct) {    // 3 tiles of 64 output channels
        __syncthreads();                // sa reads (phase4 / prev tile sw reads) done
        {
            const float4* wsrc = reinterpret_cast<const float4*>(proj_w + ct * 64 * C);
            for (int t = tid; t < 64 * 48; t += THREADS) {
                int rr = t / 48, c4 = t - rr * 48;
                sw4[rr * 49 + c4] = __ldg(wsrc + t);
            }
        }
        __syncthreads();

        const int c = ct * 64 + rloc;
        float acc[13];
        #pragma unroll
        for (int k = 0; k < 13; ++k) acc[k] = 0.f;

        #pragma unroll 4
        for (int c4 = 0; c4 < 48; ++c4) {
            const float4 wv = sw4[rloc * 49 + c4];
            #pragma unroll
            for (int k = 0; k < 13; ++k) {
                int n = nset * 13 + k; if (n > 48) n = 48;
                const float4 xv = so4[n * 48 + c4];
                acc[k] += wv.x * xv.x + wv.y * xv.y + wv.z * xv.z + wv.w * xv.w;
            }
        }

        const float pb = __ldg(proj_b + c);
        #pragma unroll
        for (int k = 0; k < 13; ++k) {
            const int n = nset * 13 + k;
            if (n < NT) yout[n * C + c] = acc[k] + pb;
        }
    }
}

extern "C" void kernel_launch(void* const* d_in, const int* in_sizes, int n_in,
                              void* d_out, int out_size)
{
    const float* x          = (const float*)d_in[0];
    const float* mask       = (const float*)d_in[1];
    const float* qkv_w      = (const float*)d_in[2];
    const float* qkv_b      = (const float*)d_in[3];
    const float* proj_w     = (const float*)d_in[4];
    const float* proj_b     = (const float*)d_in[5];
    const float* bias_table = (const float*)d_in[6];
    const int*   rel_index  = (const int*)d_in[7];

    (void)in_sizes; (void)n_in; (void)out_size;

    cudaFuncSetAttribute(win_attn_kernel,
                         cudaFuncAttributeMaxDynamicSharedMemorySize,
                         SMEM_FLOATS * (int)sizeof(float));

    win_attn_kernel<<<4096, THREADS, SMEM_FLOATS * (int)sizeof(float)>>>(
        x, mask, qkv_w, qkv_b, proj_w, proj_b, bias_table, rel_index,
        (float*)d_out);
}

// round 3
// speedup vs baseline: 1.1809x; 1.1809x over previous
#include <cuda_runtime.h>

// WindowAttention fused kernel, round 2 (resubmit after infra failure):
// broadcast/register-tiled SIMT. One CTA per window (4096 CTAs, 256 threads).

namespace {
constexpr int NT = 49;
constexpr int C  = 192;
constexpr int H  = 6;
constexpr int THREADS = 256;

// smem layout (floats)
constexpr int SX_OFF = 0;                  // x / attn-out: 49 rows, stride 196 floats (49 float4)
constexpr int SX_SZ  = 49 * 196;           // 9604
constexpr int SQ_OFF = SX_OFF + SX_SZ;     // q: [6][49][32] = 9408 (pre-scaled)
constexpr int SK_OFF = SQ_OFF + 9408;      // k: [6][49][36] = 10584 (padded)
constexpr int SV_OFF = SK_OFF + 10584;     // v: [6][49][32] = 9408
constexpr int SA_OFF = SV_OFF + 9408;      // attn [6][49][49]=14406 ; sw overlay 64x196=12544
constexpr int SMEM_FLOATS = SA_OFF + 14406;  // 53410 floats = 213,640 B
constexpr float QSCALE = 0.17677669529663687f;  // 1/sqrt(32)
}

__global__ __launch_bounds__(THREADS, 1)
void win_attn_kernel(const float* __restrict__ x,
                     const float* __restrict__ mask,
                     const float* __restrict__ qkv_w,
                     const float* __restrict__ qkv_b,
                     const float* __restrict__ proj_w,
                     const float* __restrict__ proj_b,
                     const float* __restrict__ bias_table,
                     const int*   __restrict__ rel_index,
                     float* __restrict__ out)
{
    extern __shared__ float smem[];
    float* sx = smem + SX_OFF;
    float* sq = smem + SQ_OFF;
    float* sk = smem + SK_OFF;
    float* sv = smem + SV_OFF;
    float* sa = smem + SA_OFF;

    float4* sx4 = reinterpret_cast<float4*>(sx);
    float4* sq4 = reinterpret_cast<float4*>(sq);
    float4* sk4 = reinterpret_cast<float4*>(sk);
    float4* sv4 = reinterpret_cast<float4*>(sv);
    float4* sw4 = reinterpret_cast<float4*>(sa);   // weight tile overlay, row stride 49 float4

    const int b    = blockIdx.x;
    const int w    = b & 63;
    const int tid  = threadIdx.x;
    const int lane = tid & 31;
    const int warp = tid >> 5;                     // 8 warps

    // ---------------- Phase 0: load x into padded smem (stride 196 floats) ----------------
    {
        const float4* xin = reinterpret_cast<const float4*>(x + (size_t)b * (NT * C));
        for (int t = tid; t < NT * 48; t += THREADS) {
            const int row = t / 48, c4 = t - row * 48;
            sx4[row * 49 + c4] = __ldg(xin + t);
        }
    }

    // ---------------- Phase 1: QKV GEMM ----------------
    // lanes own rows (lane, lane+32) of the 64-row tile; warp owns ~7 tokens (broadcast x).
    const int t0 = warp * 6 + (warp > 0 ? 1 : 0);  // 7 tokens per warp, slight overlap (benign dup)

    for (int rt = 0; rt < 9; ++rt) {
        __syncthreads();
        {
            const float4* wsrc = reinterpret_cast<const float4*>(qkv_w + rt * 64 * C);
            for (int t = tid; t < 64 * 48; t += THREADS) {
                const int rr = t / 48, c4 = t - rr * 48;
                sw4[rr * 49 + c4] = __ldg(wsrc + t);
            }
        }
        __syncthreads();

        float acc0[7], acc1[7];
        #pragma unroll
        for (int k = 0; k < 7; ++k) { acc0[k] = 0.f; acc1[k] = 0.f; }

        #pragma unroll 2
        for (int c4 = 0; c4 < 48; ++c4) {
            const float4 w0 = sw4[lane * 49 + c4];
            const float4 w1 = sw4[(lane + 32) * 49 + c4];
            #pragma unroll
            for (int k = 0; k < 7; ++k) {
                int t = t0 + k; if (t > 48) t = 48;
                const float4 xv = sx4[t * 49 + c4];            // warp-uniform broadcast
                acc0[k] += w0.x * xv.x + w0.y * xv.y + w0.z * xv.z + w0.w * xv.w;
                acc1[k] += w1.x * xv.x + w1.y * xv.y + w1.z * xv.z + w1.w * xv.w;
            }
        }

        const int r0 = rt * 64 + lane;
        const int r1 = r0 + 32;
        const float b0 = __ldg(qkv_b + r0);
        const float b1 = __ldg(qkv_b + r1);
        const int s0 = r0 / 192, h0 = (r0 >> 5) % 6, d0 = r0 & 31;
        const int s1 = r1 / 192, h1 = (r1 >> 5) % 6, d1 = r1 & 31;
        #pragma unroll
        for (int k = 0; k < 7; ++k) {
            const int t = t0 + k;
            if (t < NT) {
                float v0 = acc0[k] + b0;
                if (s0 == 0)      sq[(h0 * 49 + t) * 32 + d0] = v0 * QSCALE;
                else if (s0 == 1) sk[(h0 * 49 + t) * 36 + d0] = v0;
                else              sv[(h0 * 49 + t) * 32 + d0] = v0;
                float v1 = acc1[k] + b1;
                if (s1 == 0)      sq[(h1 * 49 + t) * 32 + d1] = v1 * QSCALE;
                else if (s1 == 1) sk[(h1 * 49 + t) * 36 + d1] = v1;
                else              sv[(h1 * 49 + t) * 32 + d1] = v1;
            }
        }
    }
    __syncthreads();

    // ---------------- Phase 1.5: sa = bias + mask (sw overlay dead now) ----------------
    {
        const float* mrow = mask + (size_t)w * (NT * NT);
        for (int idx = tid; idx < H * NT * NT; idx += THREADS) {
            const int h = idx / (NT * NT);
            const int rem = idx - h * (NT * NT);
            sa[idx] = __ldg(bias_table + __ldg(rel_index + rem) * H + h) + __ldg(mrow + rem);
        }
    }
    __syncthreads();

    // ---------------- Phase 2: attn += Q K^T (K in registers, Q broadcast) ----------------
    for (int task = warp; task < 24; task += 8) {
        const int h  = task >> 2;
        const int iq = task & 3;
        const int i0 = (iq == 0) ? 0 : 12 * iq + 1;   // quarters: 13,12,12,12
        const int i1 = 12 * iq + 13;

        #pragma unroll
        for (int pass = 0; pass < 2; ++pass) {
            const int j = pass * 32 + lane;
            const bool jv = (j < NT);
            const int jc = jv ? j : (NT - 1);
            float4 kreg[8];
            #pragma unroll
            for (int d4 = 0; d4 < 8; ++d4) kreg[d4] = sk4[(h * 49 + jc) * 9 + d4];

            for (int i = i0; i < i1; ++i) {
                const float4* qp = sq4 + (h * 49 + i) * 8;
                float s = 0.f;
                #pragma unroll
                for (int d4 = 0; d4 < 8; ++d4) {
                    const float4 qv = qp[d4];                  // broadcast
                    s += qv.x * kreg[d4].x + qv.y * kreg[d4].y
                       + qv.z * kreg[d4].z + qv.w * kreg[d4].w;
                }
                if (jv) sa[(h * 49 + i) * 49 + j] += s;
            }
        }
    }
    __syncthreads();

    // ---------------- Phase 3: softmax over j ----------------
    for (int row = tid; row < H * NT; row += THREADS) {
        float* p = sa + row * NT;
        float m = -1e30f;
        #pragma unroll 7
        for (int j = 0; j < NT; ++j) m = fmaxf(m, p[j]);
        float sum = 0.f;
        #pragma unroll 7
        for (int j = 0; j < NT; ++j) { const float e = __expf(p[j] - m); p[j] = e; sum += e; }
        const float inv = __frcp_rn(sum);
        #pragma unroll 7
        for (int j = 0; j < NT; ++j) p[j] *= inv;
    }
    __syncthreads();

    // ---------------- Phase 4: attn @ V -> so (sx region), V broadcast ----------------
    for (int task = warp; task < 24; task += 8) {
        const int h  = task >> 2;
        const int dq = task & 3;                       // 8 dims per quarter
        const int ia = lane;
        const int ib = lane + 32;
        const bool bv = (ib < NT);
        const int ibc = bv ? ib : (NT - 1);
        const float* apa = sa + (h * 49 + ia) * 49;
        const float* apb = sa + (h * 49 + ibc) * 49;

        float4 aA0 = {0,0,0,0}, aA1 = {0,0,0,0}, aB0 = {0,0,0,0}, aB1 = {0,0,0,0};
        for (int j = 0; j < NT; ++j) {
            const float va = apa[j];                   // lane-distinct, stride 49: CF
            const float vb = apb[j];
            const float4 v0 = sv4[(h * 49 + j) * 8 + dq * 2];      // broadcast
            const float4 v1 = sv4[(h * 49 + j) * 8 + dq * 2 + 1];
            aA0.x += va * v0.x; aA0.y += va * v0.y; aA0.z += va * v0.z; aA0.w += va * v0.w;
            aA1.x += va * v1.x; aA1.y += va * v1.y; aA1.z += va * v1.z; aA1.w += va * v1.w;
            aB0.x += vb * v0.x; aB0.y += vb * v0.y; aB0.z += vb * v0.z; aB0.w += vb * v0.w;
            aB1.x += vb * v1.x; aB1.y += vb * v1.y; aB1.z += vb * v1.z; aB1.w += vb * v1.w;
        }
        const int cbase = h * 8 + dq * 2;              // float4 column within row
        sx4[ia * 49 + cbase]     = aA0;
        sx4[ia * 49 + cbase + 1] = aA1;
        if (bv) {
            sx4[ib * 49 + cbase]     = aB0;
            sx4[ib * 49 + cbase + 1] = aB1;
        }
    }
    __syncthreads();

    // ---------------- Phase 5: proj GEMM -> gmem ----------------
    float* yout = out + (size_t)b * (NT * C);
    for (int ct = 0; ct < 3; ++ct) {
        __syncthreads();
        {
            const float4* wsrc = reinterpret_cast<const float4*>(proj_w + ct * 64 * C);
            for (int t = tid; t < 64 * 48; t += THREADS) {
                const int rr = t / 48, c4 = t - rr * 48;
                sw4[rr * 49 + c4] = __ldg(wsrc + t);
            }
        }
        __syncthreads();

        float acc0[7], acc1[7];
        #pragma unroll
        for (int k = 0; k < 7; ++k) { acc0[k] = 0.f; acc1[k] = 0.f; }

        #pragma unroll 2
        for (int c4 = 0; c4 < 48; ++c4) {
            const float4 w0 = sw4[lane * 49 + c4];
            const float4 w1 = sw4[(lane + 32) * 49 + c4];
            #pragma unroll
            for (int k = 0; k < 7; ++k) {
                int t = t0 + k; if (t > 48) t = 48;
                const float4 xv = sx4[t * 49 + c4];    // broadcast (so)
                acc0[k] += w0.x * xv.x + w0.y * xv.y + w0.z * xv.z + w0.w * xv.w;
                acc1[k] += w1.x * xv.x + w1.y * xv.y + w1.z * xv.z + w1.w * xv.w;
            }
        }

        const int c0 = ct * 64 + lane;
        const int c1 = c0 + 32;
        const float pb0 = __ldg(proj_b + c0);
        const float pb1 = __ldg(proj_b + c1);
        #pragma unroll
        for (int k = 0; k < 7; ++k) {
            const int t = t0 + k;
            if (t < NT) {
                yout[t * C + c0] = acc0[k] + pb0;
                yout[t * C + c1] = acc1[k] + pb1;
            }
        }
    }
}

extern "C" void kernel_launch(void* const* d_in, const int* in_sizes, int n_in,
                              void* d_out, int out_size)
{
    const float* x          = (const float*)d_in[0];
    const float* mask       = (const float*)d_in[1];
    const float* qkv_w      = (const float*)d_in[2];
    const float* qkv_b      = (const float*)d_in[3];
    const float* proj_w     = (const float*)d_in[4];
    const float* proj_b     = (const float*)d_in[5];
    const float* bias_table = (const float*)d_in[6];
    const int*   rel_index  = (const int*)d_in[7];

    (void)in_sizes; (void)n_in; (void)out_size;

    cudaFuncSetAttribute(win_attn_kernel,
                         cudaFuncAttributeMaxDynamicSharedMemorySize,
                         SMEM_FLOATS * (int)sizeof(float));

    win_attn_kernel<<<4096, THREADS, SMEM_FLOATS * (int)sizeof(float)>>>(
        x, mask, qkv_w, qkv_b, proj_w, proj_b, bias_table, rel_index,
        (float*)d_out);
}

// round 5
// speedup vs baseline: 1.2443x; 1.0536x over previous
#include <cuda_runtime.h>

// WindowAttention fused kernel, round 4 (resubmit after infra failure):
// packed fma.rn.f32x2 (FFMA2) everywhere. One CTA per window (4096 CTAs, 256 threads).

namespace {
constexpr int NT = 49;
constexpr int C  = 192;
constexpr int H  = 6;
constexpr int THREADS = 256;

constexpr int SX_OFF = 0;                  // x / attn-out: 49 rows, stride 196 floats
constexpr int SX_SZ  = 49 * 196;           // 9604
constexpr int SQ_OFF = SX_OFF + SX_SZ;     // q: [6][49][32] = 9408 (pre-scaled)
constexpr int SK_OFF = SQ_OFF + 9408;      // k: [6][49][36] = 10584 (padded)
constexpr int SV_OFF = SK_OFF + 10584;     // v: [6][49][32] = 9408
constexpr int SA_OFF = SV_OFF + 9408;      // attn [6][49][49]=14406 ; sw overlay 64x196=12544
constexpr int SMEM_FLOATS = SA_OFF + 14406;  // 53410 floats = 213,640 B
constexpr float QSCALE = 0.17677669529663687f;
}

// ---- packed f32x2 helpers ----
__device__ __forceinline__ void ffma2(unsigned long long& d,
                                      unsigned long long a,
                                      unsigned long long b) {
    asm("fma.rn.f32x2 %0, %1, %2, %0;" : "+l"(d) : "l"(a), "l"(b));
}
__device__ __forceinline__ float hsum2(unsigned long long p) {
    float lo, hi;
    asm("mov.b64 {%0, %1}, %2;" : "=f"(lo), "=f"(hi) : "l"(p));
    return lo + hi;
}
__device__ __forceinline__ unsigned long long dup2(float v) {
    unsigned long long r;
    asm("mov.b64 %0, {%1, %1};" : "=l"(r) : "f"(v));
    return r;
}
__device__ __forceinline__ float2 unpk2(unsigned long long p) {
    float lo, hi;
    asm("mov.b64 {%0, %1}, %2;" : "=f"(lo), "=f"(hi) : "l"(p));
    return make_float2(lo, hi);
}

__global__ __launch_bounds__(THREADS, 1)
void win_attn_kernel(const float* __restrict__ x,
                     const float* __restrict__ mask,
                     const float* __restrict__ qkv_w,
                     const float* __restrict__ qkv_b,
                     const float* __restrict__ proj_w,
                     const float* __restrict__ proj_b,
                     const float* __restrict__ bias_table,
                     const int*   __restrict__ rel_index,
                     float* __restrict__ out)
{
    extern __shared__ float smem[];
    float* sx = smem + SX_OFF;
    float* sq = smem + SQ_OFF;
    float* sk = smem + SK_OFF;
    float* sv = smem + SV_OFF;
    float* sa = smem + SA_OFF;

    float4* sx4 = reinterpret_cast<float4*>(sx);
    float4* sv4 = reinterpret_cast<float4*>(sv);
    ulonglong2* sx8 = reinterpret_cast<ulonglong2*>(sx);
    ulonglong2* sq8 = reinterpret_cast<ulonglong2*>(sq);
    ulonglong2* sk8 = reinterpret_cast<ulonglong2*>(sk);
    ulonglong2* sv8 = reinterpret_cast<ulonglong2*>(sv);
    float4*     sw4 = reinterpret_cast<float4*>(sa);
    ulonglong2* sw8 = reinterpret_cast<ulonglong2*>(sa);

    const int b    = blockIdx.x;
    const int w    = b & 63;
    const int tid  = threadIdx.x;
    const int lane = tid & 31;
    const int warp = tid >> 5;

    // ---------------- Phase 0: load x (padded rows of 196 floats) ----------------
    {
        const float4* xin = reinterpret_cast<const float4*>(x + (size_t)b * (NT * C));
        for (int t = tid; t < NT * 48; t += THREADS) {
            const int row = t / 48, c4 = t - row * 48;
            sx4[row * 49 + c4] = __ldg(xin + t);
        }
    }

    const int t0 = warp * 6 + (warp > 0 ? 1 : 0);   // 7 tokens per warp (benign overlap)

    // ---------------- Phase 1: QKV GEMM (FFMA2) ----------------
    for (int rt = 0; rt < 9; ++rt) {
        __syncthreads();
        {
            const float4* wsrc = reinterpret_cast<const float4*>(qkv_w + rt * 64 * C);
            for (int t = tid; t < 64 * 48; t += THREADS) {
                const int rr = t / 48, c4 = t - rr * 48;
                sw4[rr * 49 + c4] = __ldg(wsrc + t);
            }
        }
        __syncthreads();

        unsigned long long acc0[7], acc1[7];
        #pragma unroll
        for (int k = 0; k < 7; ++k) { acc0[k] = 0ull; acc1[k] = 0ull; }

        #pragma unroll 2
        for (int c4 = 0; c4 < 48; ++c4) {
            const ulonglong2 w0 = sw8[lane * 49 + c4];
            const ulonglong2 w1 = sw8[(lane + 32) * 49 + c4];
            #pragma unroll
            for (int k = 0; k < 7; ++k) {
                int t = t0 + k; if (t > 48) t = 48;
                const ulonglong2 xv = sx8[t * 49 + c4];        // broadcast
                ffma2(acc0[k], w0.x, xv.x);
                ffma2(acc0[k], w0.y, xv.y);
                ffma2(acc1[k], w1.x, xv.x);
                ffma2(acc1[k], w1.y, xv.y);
            }
        }

        const int r0 = rt * 64 + lane;
        const int r1 = r0 + 32;
        const float b0 = __ldg(qkv_b + r0);
        const float b1 = __ldg(qkv_b + r1);
        const int s0 = r0 / 192, h0 = (r0 >> 5) % 6, d0 = r0 & 31;
        const int s1 = r1 / 192, h1 = (r1 >> 5) % 6, d1 = r1 & 31;
        #pragma unroll
        for (int k = 0; k < 7; ++k) {
            const int t = t0 + k;
            if (t < NT) {
                float v0 = hsum2(acc0[k]) + b0;
                if (s0 == 0)      sq[(h0 * 49 + t) * 32 + d0] = v0 * QSCALE;
                else if (s0 == 1) sk[(h0 * 49 + t) * 36 + d0] = v0;
                else              sv[(h0 * 49 + t) * 32 + d0] = v0;
                float v1 = hsum2(acc1[k]) + b1;
                if (s1 == 0)      sq[(h1 * 49 + t) * 32 + d1] = v1 * QSCALE;
                else if (s1 == 1) sk[(h1 * 49 + t) * 36 + d1] = v1;
                else              sv[(h1 * 49 + t) * 32 + d1] = v1;
            }
        }
    }
    __syncthreads();

    // ---------------- Phase 1.5: sa = bias + mask ----------------
    {
        const float* mrow = mask + (size_t)w * (NT * NT);
        for (int idx = tid; idx < H * NT * NT; idx += THREADS) {
            const int h = idx / (NT * NT);
            const int rem = idx - h * (NT * NT);
            sa[idx] = __ldg(bias_table + __ldg(rel_index + rem) * H + h) + __ldg(mrow + rem);
        }
    }
    __syncthreads();

    // ---------------- Phase 2: attn += Q K^T (K in regs, Q broadcast, FFMA2) ----------------
    for (int task = warp; task < 24; task += 8) {
        const int h  = task >> 2;
        const int iq = task & 3;
        const int i0 = (iq == 0) ? 0 : 12 * iq + 1;
        const int i1 = 12 * iq + 13;

        #pragma unroll
        for (int pass = 0; pass < 2; ++pass) {
            const int j = pass * 32 + lane;
            const bool jv = (j < NT);
            const int jc = jv ? j : (NT - 1);
            ulonglong2 kreg[8];
            #pragma unroll
            for (int d4 = 0; d4 < 8; ++d4) kreg[d4] = sk8[(h * 49 + jc) * 9 + d4];

            for (int i = i0; i < i1; ++i) {
                const ulonglong2* qp = sq8 + (h * 49 + i) * 8;
                unsigned long long s = 0ull;
                #pragma unroll
                for (int d4 = 0; d4 < 8; ++d4) {
                    const ulonglong2 qv = qp[d4];              // broadcast
                    ffma2(s, qv.x, kreg[d4].x);
                    ffma2(s, qv.y, kreg[d4].y);
                }
                if (jv) sa[(h * 49 + i) * 49 + j] += hsum2(s);
            }
        }
    }
    __syncthreads();

    // ---------------- Phase 3: softmax over j ----------------
    for (int row = tid; row < H * NT; row += THREADS) {
        float* p = sa + row * NT;
        float m = -1e30f;
        #pragma unroll 7
        for (int j = 0; j < NT; ++j) m = fmaxf(m, p[j]);
        float sum = 0.f;
        #pragma unroll 7
        for (int j = 0; j < NT; ++j) { const float e = __expf(p[j] - m); p[j] = e; sum += e; }
        const float inv = __frcp_rn(sum);
        #pragma unroll 7
        for (int j = 0; j < NT; ++j) p[j] *= inv;
    }
    __syncthreads();

    // ---------------- Phase 4: attn @ V (V broadcast, FFMA2) ----------------
    for (int task = warp; task < 24; task += 8) {
        const int h  = task >> 2;
        const int dq = task & 3;
        const int ia = lane;
        const int ib = lane + 32;
        const bool bv = (ib < NT);
        const int ibc = bv ? ib : (NT - 1);
        const float* apa = sa + (h * 49 + ia) * 49;
        const float* apb = sa + (h * 49 + ibc) * 49;

        unsigned long long A00 = 0, A01 = 0, A10 = 0, A11 = 0;
        unsigned long long B00 = 0, B01 = 0, B10 = 0, B11 = 0;
        for (int j = 0; j < NT; ++j) {
            const unsigned long long va = dup2(apa[j]);        // lane-distinct, CF
            const unsigned long long vb = dup2(apb[j]);
            const ulonglong2 v0 = sv8[(h * 49 + j) * 8 + dq * 2];      // broadcast
            const ulonglong2 v1 = sv8[(h * 49 + j) * 8 + dq * 2 + 1];
            ffma2(A00, va, v0.x); ffma2(A01, va, v0.y);
            ffma2(A10, va, v1.x); ffma2(A11, va, v1.y);
            ffma2(B00, vb, v0.x); ffma2(B01, vb, v0.y);
            ffma2(B10, vb, v1.x); ffma2(B11, vb, v1.y);
        }
        const int cbase = h * 8 + dq * 2;
        {
            const float2 a = unpk2(A00), bq = unpk2(A01), c = unpk2(A10), d = unpk2(A11);
            sx4[ia * 49 + cbase]     = make_float4(a.x, a.y, bq.x, bq.y);
            sx4[ia * 49 + cbase + 1] = make_float4(c.x, c.y, d.x, d.y);
        }
        if (bv) {
            const float2 a = unpk2(B00), bq = unpk2(B01), c = unpk2(B10), d = unpk2(B11);
            sx4[ib * 49 + cbase]     = make_float4(a.x, a.y, bq.x, bq.y);
            sx4[ib * 49 + cbase + 1] = make_float4(c.x, c.y, d.x, d.y);
        }
    }
    __syncthreads();

    // ---------------- Phase 5: proj GEMM -> gmem (FFMA2) ----------------
    float* yout = out + (size_t)b * (NT * C);
    for (int ct = 0; ct < 3; ++ct) {
        __syncthreads();
        {
            const float4* wsrc = reinterpret_cast<const float4*>(proj_w + ct * 64 * C);
            for (int t = tid; t < 64 * 48; t += THREADS) {
                const int rr = t / 48, c4 = t - rr * 48;
                sw4[rr * 49 + c4] = __ldg(wsrc + t);
            }
        }
        __syncthreads();

        unsigned long long acc0[7], acc1[7];
        #pragma unroll
        for (int k = 0; k < 7; ++k) { acc0[k] = 0ull; acc1[k] = 0ull; }

        #pragma unroll 2
        for (int c4 = 0; c4 < 48; ++c4) {
            const ulonglong2 w0 = sw8[lane * 49 + c4];
            const ulonglong2 w1 = sw8[(lane + 32) * 49 + c4];
            #pragma unroll
            for (int k = 0; k < 7; ++k) {
                int t = t0 + k; if (t > 48) t = 48;
                const ulonglong2 xv = sx8[t * 49 + c4];        // broadcast (so)
                ffma2(acc0[k], w0.x, xv.x);
                ffma2(acc0[k], w0.y, xv.y);
                ffma2(acc1[k], w1.x, xv.x);
                ffma2(acc1[k], w1.y, xv.y);
            }
        }

        const int c0 = ct * 64 + lane;
        const int c1 = c0 + 32;
        const float pb0 = __ldg(proj_b + c0);
        const float pb1 = __ldg(proj_b + c1);
        #pragma unroll
        for (int k = 0; k < 7; ++k) {
            const int t = t0 + k;
            if (t < NT) {
                yout[t * C + c0] = hsum2(acc0[k]) + pb0;
                yout[t * C + c1] = hsum2(acc1[k]) + pb1;
            }
        }
    }
}

extern "C" void kernel_launch(void* const* d_in, const int* in_sizes, int n_in,
                              void* d_out, int out_size)
{
    const float* x          = (const float*)d_in[0];
    const float* mask       = (const float*)d_in[1];
    const float* qkv_w      = (const float*)d_in[2];
    const float* qkv_b      = (const float*)d_in[3];
    const float* proj_w     = (const float*)d_in[4];
    const float* proj_b     = (const float*)d_in[5];
    const float* bias_table = (const float*)d_in[6];
    const int*   rel_index  = (const int*)d_in[7];

    (void)in_sizes; (void)n_in; (void)out_size;

    cudaFuncSetAttribute(win_attn_kernel,
                         cudaFuncAttributeMaxDynamicSharedMemorySize,
                         SMEM_FLOATS * (int)sizeof(float));

    win_attn_kernel<<<4096, THREADS, SMEM_FLOATS * (int)sizeof(float)>>>(
        x, mask, qkv_w, qkv_b, proj_w, proj_b, bias_table, rel_index,
        (float*)d_out);
}

// round 7
// speedup vs baseline: 1.6484x; 1.3248x over previous
#include <cuda_runtime.h>
#include <cuda_bf16.h>
#include <cstdint>

// WindowAttention round 7: mma.sync (HMMA) bf16-split GEMMs + SIMT attention.
// K1: qkv_gemm  grid 1568 : g_qkv[n][m] (transposed) = x @ qkv_w^T + b (q pre-scaled)
// K2: attention grid 8192 : per (window, 3-head group) fp32 attention -> g_so[m][192]
// K3: proj_gemm grid 1568 : d_out = g_so @ proj_w^T + proj_b

namespace {
constexpr int MTOT = 200704;                 // 4096*49
constexpr float QSCALE = 0.17677669529663687f;

// GEMM smem (bytes): padded row-major bf16, row stride 400 B (200 bf16)
constexpr int A_HI = 0;                      // 128 x 400
constexpr int A_LO = 51200;
constexpr int B_HI = 102400;                 // 64 x 400
constexpr int B_LO = 128000;
constexpr int STG  = 153600;                 // K1: stg[n][m] 64 x 132 fp32
constexpr int K1_SMEM = STG + 64 * 132 * 4;  // 187392
constexpr int K3_SMEM = 153600;

// attention smem (floats)
constexpr int AQ = 0;            // [3][32][49]
constexpr int AK = 4704;
constexpr int AV = 9408;
constexpr int AS = 14112;        // [3][49][49]
constexpr int AO = 21315;        // [49][97]
constexpr int ATTN_FLOATS = 26068;           // 104272 B -> 2 CTAs/SM
}

__device__ __align__(16) float g_qkv[576ull * 200704ull];
__device__ __align__(16) float g_so[200704ull * 192ull];

__device__ __forceinline__ uint32_t smem_u32(const void* p) {
    uint32_t a;
    asm("{ .reg .u64 t; cvta.to.shared.u64 t, %1; cvt.u32.u64 %0, t; }" : "=r"(a) : "l"(p));
    return a;
}

__device__ __forceinline__ void ldmx4(uint32_t& r0, uint32_t& r1, uint32_t& r2, uint32_t& r3,
                                      uint32_t addr) {
    asm volatile("ldmatrix.sync.aligned.m8n8.x4.shared.b16 {%0,%1,%2,%3}, [%4];"
                 : "=r"(r0), "=r"(r1), "=r"(r2), "=r"(r3) : "r"(addr));
}

__device__ __forceinline__ void mma16816(float* c, uint32_t a0, uint32_t a1, uint32_t a2,
                                         uint32_t a3, uint32_t b0, uint32_t b1) {
    asm volatile("mma.sync.aligned.m16n8k16.row.col.f32.bf16.bf16.f32 "
                 "{%0,%1,%2,%3}, {%4,%5,%6,%7}, {%8,%9}, {%0,%1,%2,%3};"
                 : "+f"(c[0]), "+f"(c[1]), "+f"(c[2]), "+f"(c[3])
                 : "r"(a0), "r"(a1), "r"(a2), "r"(a3), "r"(b0), "r"(b1));
}

// fp32 [nrows,192] row-major -> bf16 hi/lo padded rows (stride 400 B)
__device__ __forceinline__ void stage_split(const float* __restrict__ gsrc, int nrows,
                                            char* shi, char* slo, int tid) {
    const int npairs = nrows * 96;
    for (int p = tid; p < npairs; p += 256) {
        const int r = p / 96, kp = p - r * 96;
        const float2 v = *reinterpret_cast<const float2*>(gsrc + (size_t)r * 192 + 2 * kp);
        const __nv_bfloat16 h0 = __float2bfloat16(v.x);
        const __nv_bfloat16 h1 = __float2bfloat16(v.y);
        const __nv_bfloat16 l0 = __float2bfloat16(v.x - __bfloat162float(h0));
        const __nv_bfloat16 l1 = __float2bfloat16(v.y - __bfloat162float(h1));
        const uint32_t hi = ((uint32_t)__bfloat16_as_ushort(h1) << 16) | __bfloat16_as_ushort(h0);
        const uint32_t lo = ((uint32_t)__bfloat16_as_ushort(l1) << 16) | __bfloat16_as_ushort(l0);
        const uint32_t off = (uint32_t)r * 400u + (uint32_t)kp * 4u;
        *reinterpret_cast<uint32_t*>(shi + off) = hi;
        *reinterpret_cast<uint32_t*>(slo + off) = lo;
    }
}

// 36 HMMA k-steps: hi*hi + hi*lo + lo*hi accumulated into c[8][4]
__device__ __forceinline__ void mma_tile(float (*c)[4], uint32_t sb,
                                         uint32_t aoff, uint32_t boff) {
    #pragma unroll
    for (int split = 0; split < 3; ++split) {
        const uint32_t abase = sb + (split == 2 ? A_LO : A_HI) + aoff;
        const uint32_t bbase = sb + (split == 1 ? B_LO : B_HI) + boff;
        #pragma unroll
        for (int ks = 0; ks < 12; ++ks) {
            uint32_t a0, a1, a2, a3;
            ldmx4(a0, a1, a2, a3, abase + ks * 32);
            #pragma unroll
            for (int p = 0; p < 4; ++p) {
                uint32_t b0, b1, b2, b3;
                ldmx4(b0, b1, b2, b3, bbase + p * 6400 + ks * 32);
                mma16816(c[2 * p],     a0, a1, a2, a3, b0, b1);
                mma16816(c[2 * p + 1], a0, a1, a2, a3, b2, b3);
            }
        }
    }
}

// ---------------- K1: QKV GEMM ----------------
__global__ __launch_bounds__(256, 1)
void qkv_gemm_kernel(const float* __restrict__ x,
                     const float* __restrict__ qkv_w,
                     const float* __restrict__ qkv_b) {
    extern __shared__ char smem[];
    const uint32_t sb = smem_u32(smem);
    float* stg = reinterpret_cast<float*>(smem + STG);
    const int tid = threadIdx.x, warp = tid >> 5, lane = tid & 31;
    const int mtile = blockIdx.x;
    const int g = lane >> 2, tg = lane & 3;

    stage_split(x + (size_t)mtile * 128 * 192, 128, smem + A_HI, smem + A_LO, tid);

    const uint32_t aoff = (uint32_t)(warp * 16 + (lane & 15)) * 400u + ((lane >> 4) & 1) * 16u;
    const uint32_t boff = (uint32_t)((lane & 7) + ((lane >> 4) & 1) * 8) * 400u
                        + ((lane >> 3) & 1) * 16u;

    for (int nt = 0; nt < 9; ++nt) {
        stage_split(qkv_w + (size_t)nt * 64 * 192, 64, smem + B_HI, smem + B_LO, tid);
        __syncthreads();

        float c[8][4];
        #pragma unroll
        for (int i = 0; i < 8; ++i)
            #pragma unroll
            for (int j = 0; j < 4; ++j) c[i][j] = 0.f;

        mma_tile(c, sb, aoff, boff);

        // frags -> stg[n][m] (stride 132 floats): conflict-free scalar writes
        const int m0 = warp * 16;
        #pragma unroll
        for (int p = 0; p < 4; ++p) {
            #pragma unroll
            for (int half = 0; half < 2; ++half) {
                const float* cc = c[2 * p + half];
                const int n = p * 16 + half * 8 + tg * 2;
                stg[n * 132 + m0 + g]           = cc[0];
                stg[(n + 1) * 132 + m0 + g]     = cc[1];
                stg[n * 132 + m0 + g + 8]       = cc[2];
                stg[(n + 1) * 132 + m0 + g + 8] = cc[3];
            }
        }
        __syncthreads();

        // stg -> g_qkv[nglob][m] coalesced float4
        for (int idx4 = tid; idx4 < 64 * 32; idx4 += 256) {
            const int n = idx4 >> 5, m4 = (idx4 & 31) * 4;
            const int nglob = nt * 64 + n;
            float4 v = *reinterpret_cast<const float4*>(stg + n * 132 + m4);
            const float bb = __ldg(qkv_b + nglob);
            v.x += bb; v.y += bb; v.z += bb; v.w += bb;
            if (nglob < 192) { v.x *= QSCALE; v.y *= QSCALE; v.z *= QSCALE; v.w *= QSCALE; }
            *reinterpret_cast<float4*>(&g_qkv[(size_t)nglob * MTOT + (size_t)mtile * 128 + m4]) = v;
        }
        __syncthreads();
    }
}

// ---------------- K2: attention (fp32 SIMT, 3 heads per CTA) ----------------
__global__ __launch_bounds__(256, 2)
void attn_kernel(const float* __restrict__ mask,
                 const float* __restrict__ bias_table,
                 const int* __restrict__ rel_index) {
    extern __shared__ float sf[];
    float* sq = sf + AQ;
    float* sk = sf + AK;
    float* sv = sf + AV;
    float* sa = sf + AS;
    float* so = sf + AO;

    const int tid = threadIdx.x, warp = tid >> 5, lane = tid & 31;
    const int win = blockIdx.x >> 1;
    const int hg  = blockIdx.x & 1;
    const int w   = win & 63;

    for (int idx = tid; idx < 3 * 96 * 49; idx += 256) {
        const int mat = idx / (96 * 49);
        const int rem = idx - mat * 96 * 49;
        const int rr = rem / 49, tok = rem - rr * 49;
        sf[mat * 4704 + rem] = __ldg(&g_qkv[(size_t)(mat * 192 + hg * 96 + rr) * MTOT
                                            + (size_t)win * 49 + tok]);
    }
    for (int idx = tid; idx < 3 * 2401; idx += 256) {
        const int hh = idx / 2401, rem = idx - hh * 2401;
        sa[idx] = __ldg(bias_table + __ldg(rel_index + rem) * 6 + hg * 3 + hh)
                + __ldg(mask + (size_t)w * 2401 + rem);
    }
    __syncthreads();

    for (int rowid = warp; rowid < 147; rowid += 8) {
        const int hh = rowid / 49, i = rowid - hh * 49;
        const float* qc = sq + hh * 1568 + i;
        const float* kr = sk + hh * 1568;
        float a0 = 0.f, a1 = 0.f;
        #pragma unroll 8
        for (int d = 0; d < 32; ++d) {
            const float qv = qc[d * 49];
            a0 += qv * kr[d * 49 + lane];
            a1 += qv * kr[d * 49 + lane + 32];
        }
        float* prow = sa + rowid * 49;
        prow[lane] += a0;
        if (lane < 17) prow[lane + 32] += a1;
    }
    __syncthreads();

    if (tid < 147) {
        float* p = sa + tid * 49;
        float m = -1e30f;
        #pragma unroll 7
        for (int j = 0; j < 49; ++j) m = fmaxf(m, p[j]);
        float sum = 0.f;
        #pragma unroll 7
        for (int j = 0; j < 49; ++j) { const float e = __expf(p[j] - m); p[j] = e; sum += e; }
        const float inv = __frcp_rn(sum);
        #pragma unroll 7
        for (int j = 0; j < 49; ++j) p[j] *= inv;
    }
    __syncthreads();

    for (int task = warp; task < 96; task += 8) {
        const int hh = task >> 5, d = task & 31;
        const float* ab = sa + hh * 2401;
        const float* vr = sv + hh * 1568 + d * 49;
        float a0 = 0.f, a1 = 0.f;
        #pragma unroll 7
        for (int j = 0; j < 49; ++j) {
            const float vv = vr[j];
            a0 += ab[lane * 49 + j] * vv;
            a1 += ab[(lane + 32) * 49 + j] * vv;
        }
        so[lane * 97 + hh * 32 + d] = a0;
        if (lane < 17) so[(lane + 32) * 97 + hh * 32 + d] = a1;
    }
    __syncthreads();

    for (int idx = tid; idx < 49 * 96; idx += 256) {
        const int i = idx / 96, c = idx - i * 96;
        g_so[((size_t)win * 49 + i) * 192 + hg * 96 + c] = so[i * 97 + c];
    }
}

// ---------------- K3: proj GEMM ----------------
__global__ __launch_bounds__(256, 1)
void proj_gemm_kernel(const float* __restrict__ proj_w,
                      const float* __restrict__ proj_b,
                      float* __restrict__ out) {
    extern __shared__ char smem[];
    const uint32_t sb = smem_u32(smem);
    const int tid = threadIdx.x, warp = tid >> 5, lane = tid & 31;
    const int mtile = blockIdx.x;
    const int g = lane >> 2, tg = lane & 3;

    stage_split(g_so + (size_t)mtile * 128 * 192, 128, smem + A_HI, smem + A_LO, tid);

    const uint32_t aoff = (uint32_t)(warp * 16 + (lane & 15)) * 400u + ((lane >> 4) & 1) * 16u;
    const uint32_t boff = (uint32_t)((lane & 7) + ((lane >> 4) & 1) * 8) * 400u
                        + ((lane >> 3) & 1) * 16u;

    for (int nt = 0; nt < 3; ++nt) {
        stage_split(proj_w + (size_t)nt * 64 * 192, 64, smem + B_HI, smem + B_LO, tid);
        __syncthreads();

        float c[8][4];
        #pragma unroll
        for (int i = 0; i < 8; ++i)
            #pragma unroll
            for (int j = 0; j < 4; ++j) c[i][j] = 0.f;

        mma_tile(c, sb, aoff, boff);

        // direct frag stores: float2, 32B-segment coalesced
        const size_t mbase = (size_t)mtile * 128 + warp * 16;
        #pragma unroll
        for (int p = 0; p < 4; ++p) {
            #pragma unroll
            for (int half = 0; half < 2; ++half) {
                const float* cc = c[2 * p + half];
                const int n = nt * 64 + p * 16 + half * 8 + tg * 2;
                const float b0 = __ldg(proj_b + n);
                const float b1 = __ldg(proj_b + n + 1);
                *reinterpret_cast<float2*>(&out[(mbase + g) * 192 + n]) =
                    make_float2(cc[0] + b0, cc[1] + b1);
                *reinterpret_cast<float2*>(&out[(mbase + g + 8) * 192 + n]) =
                    make_float2(cc[2] + b0, cc[3] + b1);
            }
        }
        __syncthreads();
    }
}

extern "C" void kernel_launch(void* const* d_in, const int* in_sizes, int n_in,
                              void* d_out, int out_size) {
    const float* x          = (const float*)d_in[0];
    const float* mask       = (const float*)d_in[1];
    const float* qkv_w      = (const float*)d_in[2];
    const float* qkv_b      = (const float*)d_in[3];
    const float* proj_w     = (const float*)d_in[4];
    const float* proj_b     = (const float*)d_in[5];
    const float* bias_table = (const float*)d_in[6];
    const int*   rel_index  = (const int*)d_in[7];
    (void)in_sizes; (void)n_in; (void)out_size;

    cudaFuncSetAttribute(qkv_gemm_kernel,  cudaFuncAttributeMaxDynamicSharedMemorySize, K1_SMEM);
    cudaFuncSetAttribute(proj_gemm_kernel, cudaFuncAttributeMaxDynamicSharedMemorySize, K3_SMEM);
    cudaFuncSetAttribute(attn_kernel,      cudaFuncAttributeMaxDynamicSharedMemorySize, ATTN_FLOATS * 4);

    qkv_gemm_kernel<<<1568, 256, K1_SMEM>>>(x, qkv_w, qkv_b);
    attn_kernel<<<8192, 256, ATTN_FLOATS * 4>>>(mask, bias_table, rel_index);
    proj_gemm_kernel<<<1568, 256, K3_SMEM>>>(proj_w, proj_b, (float*)d_out);
}

// round 9
// speedup vs baseline: 1.8776x; 1.1390x over previous
#include <cuda_runtime.h>
#include <cuda_bf16.h>
#include <cstdint>

// WindowAttention round 8 (resubmit after infra failure): HMMA bf16-split GEMMs
// with cp.async double-buffered pre-converted weights; direct fragment epilogues;
// coalesced attention loads.
// K0: weight prep -> g_wqh/l, g_wph/l (bf16 hi/lo)
// K1: qkv_gemm  grid 1568 : g_qkv[m][576] = x @ qkv_w^T + b (q pre-scaled)
// K2: attention grid 8192 : per (window, 3-head group) -> g_so[m][192]
// K3: proj_gemm grid 1568 : d_out = g_so @ proj_w^T + proj_b

namespace {
constexpr int MTOT = 200704;
constexpr float QSCALE = 0.17677669529663687f;

// GEMM smem (bytes): bf16 rows padded to 400 B
constexpr int A_HI = 0;                       // 128 x 400
constexpr int A_LO = 51200;
constexpr int B_BUF0 = 102400;                // each buf: hi 64x400, lo 64x400
constexpr int B_BUF_SZ = 51200;
constexpr int GEMM_SMEM = 204800;

// attention smem (floats)
constexpr int AQ = 0;
constexpr int AK = 4704;
constexpr int AV = 9408;
constexpr int AS = 14112;
constexpr int AO = 21315;
constexpr int ATTN_FLOATS = 26068;            // 104272 B -> 2 CTAs/SM
}

__device__ __align__(16) float g_qkv[(size_t)MTOT * 576];
__device__ __align__(16) float g_so[(size_t)MTOT * 192];
__device__ __align__(16) unsigned short g_wqh[576 * 192];
__device__ __align__(16) unsigned short g_wql[576 * 192];
__device__ __align__(16) unsigned short g_wph[192 * 192];
__device__ __align__(16) unsigned short g_wpl[192 * 192];

__device__ __forceinline__ uint32_t smem_u32(const void* p) {
    uint32_t a;
    asm("{ .reg .u64 t; cvta.to.shared.u64 t, %1; cvt.u32.u64 %0, t; }" : "=r"(a) : "l"(p));
    return a;
}
__device__ __forceinline__ void cp16(uint32_t dst, const void* src) {
    asm volatile("cp.async.cg.shared.global [%0], [%1], 16;" :: "r"(dst), "l"(src));
}
#define CP_COMMIT() asm volatile("cp.async.commit_group;" ::: "memory")
#define CP_WAIT(n)  asm volatile("cp.async.wait_group %0;" :: "n"(n) : "memory")

__device__ __forceinline__ void ldmx4(uint32_t& r0, uint32_t& r1, uint32_t& r2, uint32_t& r3,
                                      uint32_t addr) {
    asm volatile("ldmatrix.sync.aligned.m8n8.x4.shared.b16 {%0,%1,%2,%3}, [%4];"
                 : "=r"(r0), "=r"(r1), "=r"(r2), "=r"(r3) : "r"(addr));
}
__device__ __forceinline__ void mma16816(float* c, uint32_t a0, uint32_t a1, uint32_t a2,
                                         uint32_t a3, uint32_t b0, uint32_t b1) {
    asm volatile("mma.sync.aligned.m16n8k16.row.col.f32.bf16.bf16.f32 "
                 "{%0,%1,%2,%3}, {%4,%5,%6,%7}, {%8,%9}, {%0,%1,%2,%3};"
                 : "+f"(c[0]), "+f"(c[1]), "+f"(c[2]), "+f"(c[3])
                 : "r"(a0), "r"(a1), "r"(a2), "r"(a3), "r"(b0), "r"(b1));
}

// fp32 [nrows,192] -> bf16 hi/lo padded rows (stride 400 B)
__device__ __forceinline__ void stage_split_A(const float* __restrict__ gsrc,
                                              char* shi, char* slo, int tid) {
    for (int p = tid; p < 128 * 96; p += 256) {
        const int r = p / 96, kp = p - r * 96;
        const float2 v = *reinterpret_cast<const float2*>(gsrc + (size_t)r * 192 + 2 * kp);
        const __nv_bfloat16 h0 = __float2bfloat16(v.x);
        const __nv_bfloat16 h1 = __float2bfloat16(v.y);
        const __nv_bfloat16 l0 = __float2bfloat16(v.x - __bfloat162float(h0));
        const __nv_bfloat16 l1 = __float2bfloat16(v.y - __bfloat162float(h1));
        const uint32_t hi = ((uint32_t)__bfloat16_as_ushort(h1) << 16) | __bfloat16_as_ushort(h0);
        const uint32_t lo = ((uint32_t)__bfloat16_as_ushort(l1) << 16) | __bfloat16_as_ushort(l0);
        const uint32_t off = (uint32_t)r * 400u + (uint32_t)kp * 4u;
        *reinterpret_cast<uint32_t*>(shi + off) = hi;
        *reinterpret_cast<uint32_t*>(slo + off) = lo;
    }
}

// cp.async one 64x192 bf16 weight tile (hi+lo) into a B buffer
__device__ __forceinline__ void prefetch_B(const unsigned short* wh, const unsigned short* wl,
                                           int nt, uint32_t dhi, uint32_t dlo, int tid) {
    for (int c = tid; c < 64 * 24; c += 256) {
        const int r = c / 24, k = c - r * 24;
        const uint32_t d = (uint32_t)r * 400u + (uint32_t)k * 16u;
        cp16(dhi + d, (const char*)(wh + (size_t)(nt * 64 + r) * 192) + k * 16);
        cp16(dlo + d, (const char*)(wl + (size_t)(nt * 64 + r) * 192) + k * 16);
    }
}

// 36 HMMA k-steps: hi*hi + hi*lo + lo*hi
__device__ __forceinline__ void mma_tile(float (*c)[4], uint32_t ahi, uint32_t alo,
                                         uint32_t bhi, uint32_t blo) {
    #pragma unroll
    for (int split = 0; split < 3; ++split) {
        const uint32_t abase = (split == 2) ? alo : ahi;
        const uint32_t bbase = (split == 1) ? blo : bhi;
        #pragma unroll
        for (int ks = 0; ks < 12; ++ks) {
            uint32_t a0, a1, a2, a3;
            ldmx4(a0, a1, a2, a3, abase + ks * 32);
            #pragma unroll
            for (int p = 0; p < 4; ++p) {
                uint32_t b0, b1, b2, b3;
                ldmx4(b0, b1, b2, b3, bbase + p * 6400 + ks * 32);
                mma16816(c[2 * p],     a0, a1, a2, a3, b0, b1);
                mma16816(c[2 * p + 1], a0, a1, a2, a3, b2, b3);
            }
        }
    }
}

// ---------------- K0: weight prep ----------------
__global__ __launch_bounds__(256)
void prep_kernel(const float* __restrict__ qkv_w, const float* __restrict__ proj_w) {
    const int idx = blockIdx.x * 256 + threadIdx.x;
    const int NQ = 576 * 192;
    if (idx < NQ) {
        const float v = qkv_w[idx];
        const __nv_bfloat16 h = __float2bfloat16(v);
        g_wqh[idx] = __bfloat16_as_ushort(h);
        g_wql[idx] = __bfloat16_as_ushort(__float2bfloat16(v - __bfloat162float(h)));
    }
    if (idx < 192 * 192) {
        const float v = proj_w[idx];
        const __nv_bfloat16 h = __float2bfloat16(v);
        g_wph[idx] = __bfloat16_as_ushort(h);
        g_wpl[idx] = __bfloat16_as_ushort(__float2bfloat16(v - __bfloat162float(h)));
    }
}

// ---------------- K1: QKV GEMM ----------------
__global__ __launch_bounds__(256, 1)
void qkv_gemm_kernel(const float* __restrict__ x, const float* __restrict__ qkv_b) {
    extern __shared__ char smem[];
    const uint32_t sb = smem_u32(smem);
    const int tid = threadIdx.x, warp = tid >> 5, lane = tid & 31;
    const int mtile = blockIdx.x;
    const int g = lane >> 2, tg = lane & 3;

    prefetch_B(g_wqh, g_wql, 0, sb + B_BUF0, sb + B_BUF0 + 25600, tid);
    CP_COMMIT();

    stage_split_A(x + (size_t)mtile * 128 * 192, smem + A_HI, smem + A_LO, tid);

    const uint32_t aoff = (uint32_t)(warp * 16 + (lane & 15)) * 400u + ((lane >> 4) & 1) * 16u;
    const uint32_t boff = (uint32_t)((lane & 7) + ((lane >> 4) & 1) * 8) * 400u
                        + ((lane >> 3) & 1) * 16u;
    const uint32_t ahi = sb + A_HI + aoff, alo = sb + A_LO + aoff;

    for (int nt = 0; nt < 9; ++nt) {
        const uint32_t bbase = sb + B_BUF0 + (nt & 1) * B_BUF_SZ;
        if (nt + 1 < 9) {
            prefetch_B(g_wqh, g_wql, nt + 1,
                       sb + B_BUF0 + ((nt + 1) & 1) * B_BUF_SZ,
                       sb + B_BUF0 + ((nt + 1) & 1) * B_BUF_SZ + 25600, tid);
            CP_COMMIT();
            CP_WAIT(1);
        } else {
            CP_WAIT(0);
        }
        __syncthreads();

        float c[8][4];
        #pragma unroll
        for (int i = 0; i < 8; ++i)
            #pragma unroll
            for (int j = 0; j < 4; ++j) c[i][j] = 0.f;

        mma_tile(c, ahi, alo, bbase + boff, bbase + 25600 + boff);

        // direct fragment epilogue -> g_qkv[m][576]
        const size_t mbase = (size_t)mtile * 128 + warp * 16;
        #pragma unroll
        for (int p = 0; p < 4; ++p) {
            #pragma unroll
            for (int half = 0; half < 2; ++half) {
                const float* cc = c[2 * p + half];
                const int n = nt * 64 + p * 16 + half * 8 + tg * 2;
                float b0 = __ldg(qkv_b + n);
                float b1 = __ldg(qkv_b + n + 1);
                float s = (n < 192) ? QSCALE : 1.f;
                *reinterpret_cast<float2*>(&g_qkv[(mbase + g) * 576 + n]) =
                    make_float2((cc[0] + b0) * s, (cc[1] + b1) * s);
                *reinterpret_cast<float2*>(&g_qkv[(mbase + g + 8) * 576 + n]) =
                    make_float2((cc[2] + b0) * s, (cc[3] + b1) * s);
            }
        }
        __syncthreads();   // done reading buf[nt&1] before it is refilled at nt+2
    }
}

// ---------------- K2: attention ----------------
__global__ __launch_bounds__(256, 2)
void attn_kernel(const float* __restrict__ mask,
                 const float* __restrict__ bias_table,
                 const int* __restrict__ rel_index) {
    extern __shared__ float sf[];
    float* sq = sf + AQ;
    float* sk = sf + AK;
    float* sv = sf + AV;
    float* sa = sf + AS;
    float* so = sf + AO;

    const int tid = threadIdx.x, warp = tid >> 5, lane = tid & 31;
    const int win = blockIdx.x >> 1;
    const int hg  = blockIdx.x & 1;
    const int w   = win & 63;

    // coalesced: rr fastest (runs of 96 floats); smem stride-49 writes (CF)
    for (int idx = tid; idx < 3 * 49 * 96; idx += 256) {
        const int mat = idx / (49 * 96);
        const int rem = idx - mat * (49 * 96);
        const int tok = rem / 96, rr = rem - tok * 96;
        sf[mat * 4704 + rr * 49 + tok] =
            __ldg(&g_qkv[((size_t)win * 49 + tok) * 576 + mat * 192 + hg * 96 + rr]);
    }
    for (int idx = tid; idx < 3 * 2401; idx += 256) {
        const int hh = idx / 2401, rem = idx - hh * 2401;
        sa[idx] = __ldg(bias_table + __ldg(rel_index + rem) * 6 + hg * 3 + hh)
                + __ldg(mask + (size_t)w * 2401 + rem);
    }
    __syncthreads();

    for (int rowid = warp; rowid < 147; rowid += 8) {
        const int hh = rowid / 49, i = rowid - hh * 49;
        const float* qc = sq + hh * 1568 + i;
        const float* kr = sk + hh * 1568;
        float a0 = 0.f, a1 = 0.f;
        #pragma unroll 8
        for (int d = 0; d < 32; ++d) {
            const float qv = qc[d * 49];
            a0 += qv * kr[d * 49 + lane];
            a1 += qv * kr[d * 49 + lane + 32];
        }
        float* prow = sa + rowid * 49;
        prow[lane] += a0;
        if (lane < 17) prow[lane + 32] += a1;
    }
    __syncthreads();

    if (tid < 147) {
        float* p = sa + tid * 49;
        float m = -1e30f;
        #pragma unroll 7
        for (int j = 0; j < 49; ++j) m = fmaxf(m, p[j]);
        float sum = 0.f;
        #pragma unroll 7
        for (int j = 0; j < 49; ++j) { const float e = __expf(p[j] - m); p[j] = e; sum += e; }
        const float inv = __frcp_rn(sum);
        #pragma unroll 7
        for (int j = 0; j < 49; ++j) p[j] *= inv;
    }
    __syncthreads();

    for (int task = warp; task < 96; task += 8) {
        const int hh = task >> 5, d = task & 31;
        const float* ab = sa + hh * 2401;
        const float* vr = sv + hh * 1568 + d * 49;
        float a0 = 0.f, a1 = 0.f;
        #pragma unroll 7
        for (int j = 0; j < 49; ++j) {
            const float vv = vr[j];
            a0 += ab[lane * 49 + j] * vv;
            a1 += ab[(lane + 32) * 49 + j] * vv;
        }
        so[lane * 97 + hh * 32 + d] = a0;
        if (lane < 17) so[(lane + 32) * 97 + hh * 32 + d] = a1;
    }
    __syncthreads();

    for (int idx = tid; idx < 49 * 96; idx += 256) {
        const int i = idx / 96, c = idx - i * 96;
        g_so[((size_t)win * 49 + i) * 192 + hg * 96 + c] = so[i * 97 + c];
    }
}

// ---------------- K3: proj GEMM ----------------
__global__ __launch_bounds__(256, 1)
void proj_gemm_kernel(const float* __restrict__ proj_b, float* __restrict__ out) {
    extern __shared__ char smem[];
    const uint32_t sb = smem_u32(smem);
    const int tid = threadIdx.x, warp = tid >> 5, lane = tid & 31;
    const int mtile = blockIdx.x;
    const int g = lane >> 2, tg = lane & 3;

    prefetch_B(g_wph, g_wpl, 0, sb + B_BUF0, sb + B_BUF0 + 25600, tid);
    CP_COMMIT();

    stage_split_A(g_so + (size_t)mtile * 128 * 192, smem + A_HI, smem + A_LO, tid);

    const uint32_t aoff = (uint32_t)(warp * 16 + (lane & 15)) * 400u + ((lane >> 4) & 1) * 16u;
    const uint32_t boff = (uint32_t)((lane & 7) + ((lane >> 4) & 1) * 8) * 400u
                        + ((lane >> 3) & 1) * 16u;
    const uint32_t ahi = sb + A_HI + aoff, alo = sb + A_LO + aoff;

    for (int nt = 0; nt < 3; ++nt) {
        const uint32_t bbase = sb + B_BUF0 + (nt & 1) * B_BUF_SZ;
        if (nt + 1 < 3) {
            prefetch_B(g_wph, g_wpl, nt + 1,
                       sb + B_BUF0 + ((nt + 1) & 1) * B_BUF_SZ,
                       sb + B_BUF0 + ((nt + 1) & 1) * B_BUF_SZ + 25600, tid);
            CP_COMMIT();
            CP_WAIT(1);
        } else {
            CP_WAIT(0);
        }
        __syncthreads();

        float c[8][4];
        #pragma unroll
        for (int i = 0; i < 8; ++i)
            #pragma unroll
            for (int j = 0; j < 4; ++j) c[i][j] = 0.f;

        mma_tile(c, ahi, alo, bbase + boff, bbase + 25600 + boff);

        const size_t mbase = (size_t)mtile * 128 + warp * 16;
        #pragma unroll
        for (int p = 0; p < 4; ++p) {
            #pragma unroll
            for (int half = 0; half < 2; ++half) {
                const float* cc = c[2 * p + half];
                const int n = nt * 64 + p * 16 + half * 8 + tg * 2;
                const float b0 = __ldg(proj_b + n);
                const float b1 = __ldg(proj_b + n + 1);
                *reinterpret_cast<float2*>(&out[(mbase + g) * 192 + n]) =
                    make_float2(cc[0] + b0, cc[1] + b1);
                *reinterpret_cast<float2*>(&out[(mbase + g + 8) * 192 + n]) =
                    make_float2(cc[2] + b0, cc[3] + b1);
            }
        }
        __syncthreads();
    }
}

extern "C" void kernel_launch(void* const* d_in, const int* in_sizes, int n_in,
                              void* d_out, int out_size) {
    const float* x          = (const float*)d_in[0];
    const float* mask       = (const float*)d_in[1];
    const float* qkv_w      = (const float*)d_in[2];
    const float* qkv_b      = (const float*)d_in[3];
    const float* proj_w     = (const float*)d_in[4];
    const float* proj_b     = (const float*)d_in[5];
    const float* bias_table = (const float*)d_in[6];
    const int*   rel_index  = (const int*)d_in[7];
    (void)in_sizes; (void)n_in; (void)out_size;

    cudaFuncSetAttribute(qkv_gemm_kernel,  cudaFuncAttributeMaxDynamicSharedMemorySize, GEMM_SMEM);
    cudaFuncSetAttribute(proj_gemm_kernel, cudaFuncAttributeMaxDynamicSharedMemorySize, GEMM_SMEM);
    cudaFuncSetAttribute(attn_kernel,      cudaFuncAttributeMaxDynamicSharedMemorySize, ATTN_FLOATS * 4);

    prep_kernel<<<432, 256>>>(qkv_w, proj_w);
    qkv_gemm_kernel<<<1568, 256, GEMM_SMEM>>>(x, qkv_b);
    attn_kernel<<<8192, 256, ATTN_FLOATS * 4>>>(mask, bias_table, rel_index);
    proj_gemm_kernel<<<1568, 256, GEMM_SMEM>>>(proj_b, (float*)d_out);
}